// round 16
// baseline (speedup 1.0000x reference)
#include <cuda_runtime.h>

#define NB 32
#define NS 4096
#define ND 1024
#define NEGV -1e37f

#define SCHUNK 512
#define NCH (NS / SCHUNK)   // 8 chunks
#define NQ 4                // D-quarters per chunk

// scratch: logits then softmax weights [B, S]
__device__ float g_logits[NB * NS];
// partial PV sums [B, NCH, D] = 1 MB
__device__ float g_part[NB * NCH * ND];

// ---------------------------------------------------------------------------
// Kernel 1 (R11-identical): logits[b,s] = q[b] . k[b,s]; masked rows skip the
// K read and get NEG. 8 warps, one s-row each; q staged in shared; K __ldcs.
// ---------------------------------------------------------------------------
__global__ __launch_bounds__(256) void qk_kernel(
    const float* __restrict__ keys,
    const float* __restrict__ queries,
    const int* __restrict__ mask)
{
    const int rows_per_block = 8;
    int b  = blockIdx.x / (NS / rows_per_block);
    int s0 = (blockIdx.x % (NS / rows_per_block)) * rows_per_block;

    __shared__ float4 qs[ND / 4];
    qs[threadIdx.x] = ((const float4*)(queries + (size_t)b * ND))[threadIdx.x];
    __syncthreads();

    int warp = threadIdx.x >> 5;
    int lane = threadIdx.x & 31;
    int s = s0 + warp;

    if (mask[b * NS + s] == 0) {
        if (lane == 0) g_logits[b * NS + s] = NEGV;
        return;
    }

    const float4* k4 = (const float4*)(keys + ((size_t)b * NS + s) * ND);
    float acc = 0.f;
#pragma unroll
    for (int i = 0; i < 8; i++) {
        int idx = i * 32 + lane;          // 0..255 float4s
        float4 kv = __ldcs(&k4[idx]);
        float4 qv = qs[idx];
        acc += kv.x * qv.x + kv.y * qv.y + kv.z * qv.z + kv.w * qv.w;
    }
#pragma unroll
    for (int o = 16; o; o >>= 1)
        acc += __shfl_xor_sync(0xFFFFFFFFu, acc, o);

    if (lane == 0) g_logits[b * NS + s] = acc;
}

// ---------------------------------------------------------------------------
// Kernel 2 (R11-identical): per-batch softmax over S=4096.
// ---------------------------------------------------------------------------
__global__ __launch_bounds__(1024) void softmax_kernel()
{
    int b = blockIdx.x;
    int t = threadIdx.x;
    float* row = g_logits + b * NS;

    float v0 = row[t];
    float v1 = row[t + 1024];
    float v2 = row[t + 2048];
    float v3 = row[t + 3072];

    __shared__ float red[32];

    float m = fmaxf(fmaxf(v0, v1), fmaxf(v2, v3));
#pragma unroll
    for (int o = 16; o; o >>= 1) m = fmaxf(m, __shfl_xor_sync(0xFFFFFFFFu, m, o));
    if ((t & 31) == 0) red[t >> 5] = m;
    __syncthreads();
    if (t < 32) {
        float x = red[t];
#pragma unroll
        for (int o = 16; o; o >>= 1) x = fmaxf(x, __shfl_xor_sync(0xFFFFFFFFu, x, o));
        red[t] = x;
    }
    __syncthreads();
    m = red[0];
    __syncthreads();

    float e0 = __expf(v0 - m);
    float e1 = __expf(v1 - m);
    float e2 = __expf(v2 - m);
    float e3 = __expf(v3 - m);
    float s = e0 + e1 + e2 + e3;
#pragma unroll
    for (int o = 16; o; o >>= 1) s += __shfl_xor_sync(0xFFFFFFFFu, s, o);
    if ((t & 31) == 0) red[t >> 5] = s;
    __syncthreads();
    if (t < 32) {
        float x = red[t];
#pragma unroll
        for (int o = 16; o; o >>= 1) x += __shfl_xor_sync(0xFFFFFFFFu, x, o);
        red[t] = x;
    }
    __syncthreads();
    float inv = 1.0f / red[0];

    row[t]        = e0 * inv;
    row[t + 1024] = e1 * inv;
    row[t + 2048] = e2 * inv;
    row[t + 3072] = e3 * inv;
}

// ---------------------------------------------------------------------------
// Kernel 3: partial PV. Block = (b, 512-row chunk, 256-float D-quarter).
// Grid = 32*8*4 = 1024 blocks (proven occupancy), 256 threads.
// Thread owns one float4 column of its quarter; walks 4 rows/step, 128 steps,
// unroll-4 predicated __ldcs loads (row weight 0 -> skip, per-row 1KB strips).
// Fixed-order combine of the 4 row-offset groups -> g_part[b][chunk][quarter].
// ---------------------------------------------------------------------------
__global__ __launch_bounds__(256) void pv_kernel(const float* __restrict__ values)
{
    int quarter = blockIdx.x & (NQ - 1);
    int chunk   = (blockIdx.x >> 2) & (NCH - 1);
    int b       = blockIdx.x >> 5;
    int s0      = chunk * SCHUNK;

    __shared__ float  ws[SCHUNK];
    __shared__ float4 sp[256];

    int t = threadIdx.x;
    ws[t]       = g_logits[b * NS + s0 + t];
    ws[t + 256] = g_logits[b * NS + s0 + 256 + t];
    __syncthreads();

    int qcol   = quarter * 64 + (t & 63);   // float4 column 0..255 of full row
    int rowoff = t >> 6;                    // 0..3

    const float4* v4 = (const float4*)(values + ((size_t)b * NS + s0) * ND) + qcol;

    float4 acc = make_float4(0.f, 0.f, 0.f, 0.f);
#pragma unroll 4
    for (int i = 0; i < SCHUNK / 4; i++) {
        int r = i * 4 + rowoff;
        float w = ws[r];
        float4 v = make_float4(0.f, 0.f, 0.f, 0.f);
        if (w != 0.f) v = __ldcs(&v4[(size_t)r * (ND / 4)]);
        acc.x += w * v.x; acc.y += w * v.y; acc.z += w * v.z; acc.w += w * v.w;
    }

    sp[t] = acc;
    __syncthreads();

    if (rowoff == 0) {
        float4 a1 = sp[t + 64], a2 = sp[t + 128], a3 = sp[t + 192];
        acc.x += a1.x + a2.x + a3.x;
        acc.y += a1.y + a2.y + a3.y;
        acc.z += a1.z + a2.z + a3.z;
        acc.w += a1.w + a2.w + a3.w;
        ((float4*)g_part)[(size_t)(b * NCH + chunk) * (ND / 4) + qcol] = acc;
    }
}

// ---------------------------------------------------------------------------
// Kernel 4: out[b,:] = sum over 8 chunks of g_part[b,c,:] (1 MB total).
// 256 blocks x 256 threads; thread t: chunk = t>>5, slot = t&31.
// One coalesced LDG.128 per thread; fixed-order shared combine.
// ---------------------------------------------------------------------------
__global__ __launch_bounds__(256) void reduce_kernel(float* __restrict__ out)
{
    int t    = threadIdx.x;
    int c    = t >> 5;                 // chunk 0..7
    int slot = t & 31;
    int o  = blockIdx.x * 32 + slot;   // 0..8191 global float4 output index
    int b  = o >> 8;
    int d4 = o & 255;

    float4 acc = ((const float4*)g_part)[((size_t)(b * NCH + c)) * (ND / 4) + d4];

    __shared__ float4 sp[7 * 32];      // chunks 1..7
    if (c > 0) sp[(c - 1) * 32 + slot] = acc;
    __syncthreads();

    if (c == 0) {
#pragma unroll
        for (int i = 0; i < 7; i++) {
            float4 v = sp[i * 32 + slot];
            acc.x += v.x; acc.y += v.y; acc.z += v.z; acc.w += v.w;
        }
        ((float4*)out)[o] = acc;
    }
}

// ---------------------------------------------------------------------------
extern "C" void kernel_launch(void* const* d_in, const int* in_sizes, int n_in,
                              void* d_out, int out_size)
{
    const float* keys    = (const float*)d_in[0];
    const float* queries = (const float*)d_in[1];
    const float* values  = (const float*)d_in[2];
    const int*   mask    = (const int*)d_in[3];
    float* out = (float*)d_out;

    qk_kernel<<<NB * (NS / 8), 256>>>(keys, queries, mask);
    softmax_kernel<<<NB, 1024>>>();
    pv_kernel<<<NB * NCH * NQ, 256>>>(values);
    reduce_kernel<<<256, 256>>>(out);
}

// round 17
// speedup vs baseline: 1.1140x; 1.1140x over previous
#include <cuda_runtime.h>

#define NB 32
#define NS 4096
#define ND 1024
#define NEGV -1e37f

#define SCHUNK 128
#define NCH (NS / SCHUNK)   // 32

// scratch: logits then softmax weights [B, S]
__device__ float g_logits[NB * NS];

// ---------------------------------------------------------------------------
// Kernel 1: logits[b,s] = q[b] . k[b,s]  (masked rows: skip K read, write NEG)
// Also zeroes this block's 2-float slice of out (poisoned by harness) so pv
// can accumulate into it atomically. 8 warps, one s-row each; K loads __ldcs.
// Mask is int32 (JAX bool widened): nonzero = valid.
// ---------------------------------------------------------------------------
__global__ __launch_bounds__(256) void qk_kernel(
    const float* __restrict__ keys,
    const float* __restrict__ queries,
    const int* __restrict__ mask,
    float* __restrict__ out)
{
    const int rows_per_block = 8;
    int b  = blockIdx.x / (NS / rows_per_block);
    int s0 = (blockIdx.x % (NS / rows_per_block)) * rows_per_block;

    // zero 2 floats of out per block (16384 blocks x 2 = 32768 floats)
    if (threadIdx.x < 2)
        out[blockIdx.x * 2 + threadIdx.x] = 0.0f;

    __shared__ float4 qs[ND / 4];
    qs[threadIdx.x] = ((const float4*)(queries + (size_t)b * ND))[threadIdx.x];
    __syncthreads();

    int warp = threadIdx.x >> 5;
    int lane = threadIdx.x & 31;
    int s = s0 + warp;

    if (mask[b * NS + s] == 0) {
        if (lane == 0) g_logits[b * NS + s] = NEGV;
        return;
    }

    const float4* k4 = (const float4*)(keys + ((size_t)b * NS + s) * ND);
    float acc = 0.f;
#pragma unroll
    for (int i = 0; i < 8; i++) {
        int idx = i * 32 + lane;          // 0..255 float4s
        float4 kv = __ldcs(&k4[idx]);
        float4 qv = qs[idx];
        acc += kv.x * qv.x + kv.y * qv.y + kv.z * qv.z + kv.w * qv.w;
    }
#pragma unroll
    for (int o = 16; o; o >>= 1)
        acc += __shfl_xor_sync(0xFFFFFFFFu, acc, o);

    if (lane == 0) g_logits[b * NS + s] = acc;
}

// ---------------------------------------------------------------------------
// Kernel 2: per-batch softmax over S=4096. One block of 1024 threads per batch.
// Masked logits (-1e37) underflow to exactly 0.0f after exp.
// ---------------------------------------------------------------------------
__global__ __launch_bounds__(1024) void softmax_kernel()
{
    int b = blockIdx.x;
    int t = threadIdx.x;
    float* row = g_logits + b * NS;

    float v0 = row[t];
    float v1 = row[t + 1024];
    float v2 = row[t + 2048];
    float v3 = row[t + 3072];

    __shared__ float red[32];

    // ---- max reduce ----
    float m = fmaxf(fmaxf(v0, v1), fmaxf(v2, v3));
#pragma unroll
    for (int o = 16; o; o >>= 1) m = fmaxf(m, __shfl_xor_sync(0xFFFFFFFFu, m, o));
    if ((t & 31) == 0) red[t >> 5] = m;
    __syncthreads();
    if (t < 32) {
        float x = red[t];
#pragma unroll
        for (int o = 16; o; o >>= 1) x = fmaxf(x, __shfl_xor_sync(0xFFFFFFFFu, x, o));
        red[t] = x;
    }
    __syncthreads();
    m = red[0];
    __syncthreads();

    // ---- exp + sum reduce ----
    float e0 = __expf(v0 - m);
    float e1 = __expf(v1 - m);
    float e2 = __expf(v2 - m);
    float e3 = __expf(v3 - m);
    float s = e0 + e1 + e2 + e3;
#pragma unroll
    for (int o = 16; o; o >>= 1) s += __shfl_xor_sync(0xFFFFFFFFu, s, o);
    if ((t & 31) == 0) red[t >> 5] = s;
    __syncthreads();
    if (t < 32) {
        float x = red[t];
#pragma unroll
        for (int o = 16; o; o >>= 1) x += __shfl_xor_sync(0xFFFFFFFFu, x, o);
        red[t] = x;
    }
    __syncthreads();
    float inv = 1.0f / red[0];

    row[t]        = e0 * inv;
    row[t + 1024] = e1 * inv;
    row[t + 2048] = e2 * inv;
    row[t + 3072] = e3 * inv;
}

// ---------------------------------------------------------------------------
// Kernel 3: PV. Block = (b, 128-row s-chunk), 1024 blocks total.
// 256 threads, each owns a float4 of D. Skips V rows whose weight is exactly 0
// (masked). V loads __ldcs. Accumulates directly into out via atomicAdd
// (32 contributions per output element, L2-resident) — no partials, no reduce.
// ---------------------------------------------------------------------------
__global__ __launch_bounds__(256) void pv_kernel(
    const float* __restrict__ values,
    float* __restrict__ out)
{
    int chunk = blockIdx.x & (NCH - 1);
    int b     = blockIdx.x / NCH;
    int s0    = chunk * SCHUNK;

    __shared__ float ws[SCHUNK];
    int t = threadIdx.x;
    if (t < SCHUNK) ws[t] = g_logits[b * NS + s0 + t];
    __syncthreads();

    const float4* v4 = (const float4*)(values + ((size_t)b * NS + s0) * ND);
    float4 acc = make_float4(0.f, 0.f, 0.f, 0.f);

#pragma unroll 4
    for (int i = 0; i < SCHUNK; i += 4) {
        float w0 = ws[i], w1 = ws[i + 1], w2 = ws[i + 2], w3 = ws[i + 3];
        float4 a = make_float4(0.f, 0.f, 0.f, 0.f);
        float4 c = make_float4(0.f, 0.f, 0.f, 0.f);
        float4 d = make_float4(0.f, 0.f, 0.f, 0.f);
        float4 e = make_float4(0.f, 0.f, 0.f, 0.f);
        if (w0 != 0.f) a = __ldcs(&v4[(size_t)(i + 0) * (ND / 4) + t]);
        if (w1 != 0.f) c = __ldcs(&v4[(size_t)(i + 1) * (ND / 4) + t]);
        if (w2 != 0.f) d = __ldcs(&v4[(size_t)(i + 2) * (ND / 4) + t]);
        if (w3 != 0.f) e = __ldcs(&v4[(size_t)(i + 3) * (ND / 4) + t]);
        acc.x += w0 * a.x; acc.y += w0 * a.y; acc.z += w0 * a.z; acc.w += w0 * a.w;
        acc.x += w1 * c.x; acc.y += w1 * c.y; acc.z += w1 * c.z; acc.w += w1 * c.w;
        acc.x += w2 * d.x; acc.y += w2 * d.y; acc.z += w2 * d.z; acc.w += w2 * d.w;
        acc.x += w3 * e.x; acc.y += w3 * e.y; acc.z += w3 * e.z; acc.w += w3 * e.w;
    }

    float* o = out + (size_t)b * ND + t * 4;
    atomicAdd(o + 0, acc.x);
    atomicAdd(o + 1, acc.y);
    atomicAdd(o + 2, acc.z);
    atomicAdd(o + 3, acc.w);
}

// ---------------------------------------------------------------------------
extern "C" void kernel_launch(void* const* d_in, const int* in_sizes, int n_in,
                              void* d_out, int out_size)
{
    const float* keys    = (const float*)d_in[0];
    const float* queries = (const float*)d_in[1];
    const float* values  = (const float*)d_in[2];
    const int*   mask    = (const int*)d_in[3];
    float* out = (float*)d_out;

    qk_kernel<<<NB * (NS / 8), 256>>>(keys, queries, mask, out);
    softmax_kernel<<<NB, 1024>>>();
    pv_kernel<<<NB * NCH, 256>>>(values, out);
}